// round 12
// baseline (speedup 1.0000x reference)
#include <cuda_runtime.h>
#include <cstdint>
#include <cstddef>

namespace {
constexpr int Bn = 64, Sn = 512, In = 512, Hn = 1024, On = 512;
constexpr int COMBn = In + Hn;          // 1536
constexpr int NG = 128, NY = 16, NB = NG + NY;   // 144 CTAs
constexpr int NT = 512;                 // 16 warps
constexpr int RC = 8, NCH = Bn / RC;    // 8 rows per staged chunk, 8 chunks
// gate A layout: per row, 64 slices x (24 + 4 pad) floats; quad phase = 7*sl+j mod 8
constexpr int G_K   = 24;
constexpr int G_SLP = G_K + 4;          // 28
constexpr int G_ROW = 64 * G_SLP;       // 1792 floats per A row
// y A layout: per row, 64 slices x (16 + 4 pad) floats; quad phase = 5*sl+j mod 8
constexpr int Y_K   = 16;
constexpr int Y_SLP = Y_K + 4;          // 20
constexpr int Y_ROW = 64 * Y_SLP;       // 1280
constexpr int P_LD = 65;
constexpr int SP_PLANE = 32 * P_LD;     // 2080 floats per k-half plane
constexpr int SMEM_FLOATS = 2 * RC * G_ROW + 2 * SP_PLANE;  // 28672 + 4160
constexpr int SMEM_BYTES = SMEM_FLOATS * 4;                 // 131328
}

__device__ float g_h[2 * Bn * Hn];           // h double buffer
__device__ unsigned g_count = 0;             // barrier arrivals
__device__ volatile unsigned g_gen = 0;      // barrier generation

__device__ __forceinline__ void cp16(unsigned dst, const float* src) {
    asm volatile("cp.async.cg.shared.global [%0], [%1], 16;" :: "r"(dst), "l"(src));
}
__device__ __forceinline__ void cp_commit() {
    asm volatile("cp.async.commit_group;" ::: "memory");
}
template <int N>
__device__ __forceinline__ void cp_wait() {
    asm volatile("cp.async.wait_group %0;" :: "n"(N) : "memory");
}

// Packed fp32 pair FMA (SASS FFMA2): acc.{lo,hi} += a.{lo,hi} * w.{lo,hi}
#define FMA2(acc, aa, ww) \
    asm("fma.rn.f32x2 %0, %1, %2, %0;" : "+l"(acc) : "l"(aa), "l"(ww))

__device__ __forceinline__ float psum(unsigned long long v) {
    return __uint_as_float((unsigned)v) + __uint_as_float((unsigned)(v >> 32));
}
__device__ __forceinline__ float sigm(float v) {
    return 1.0f / (1.0f + __expf(-v));
}

__device__ __forceinline__ void grid_barrier() {
    __syncthreads();
    if (threadIdx.x == 0) {
        __threadfence();                       // release h writes
        unsigned my = g_gen;
        if (atomicAdd(&g_count, 1u) == (unsigned)(NB - 1)) {
            g_count = 0u;
            __threadfence();
            g_gen = my + 1u;
        } else {
            while (g_gen == my) { }
            __threadfence();                   // acquire
        }
    }
    __syncthreads();
}

// Reduce 4 values over 32 lanes in 6 shfls. Lanes 0-7 -> v0, 8-15 -> v2,
// 16-23 -> v1, 24-31 -> v3.
__device__ __forceinline__ float reduce4(float v0, float v1, float v2, float v3, int lane) {
    bool hi16 = (lane & 16) != 0;
    float a  = hi16 ? v1 : v0;
    float ta = hi16 ? v0 : v1;
    a += __shfl_xor_sync(0xFFFFFFFFu, ta, 16);
    float b  = hi16 ? v3 : v2;
    float tb = hi16 ? v2 : v3;
    b += __shfl_xor_sync(0xFFFFFFFFu, tb, 16);
    bool hi8 = (lane & 8) != 0;
    float c  = hi8 ? b : a;
    float tc = hi8 ? a : b;
    c += __shfl_xor_sync(0xFFFFFFFFu, tc, 8);
    c += __shfl_xor_sync(0xFFFFFFFFu, c, 4);
    c += __shfl_xor_sync(0xFFFFFFFFu, c, 2);
    c += __shfl_xor_sync(0xFFFFFFFFu, c, 1);
    return c;
}

__global__ void __launch_bounds__(NT) lstm_fused(
    const float* __restrict__ x,  const float* __restrict__ h0, const float* __restrict__ c0,
    const float* __restrict__ Wf, const float* __restrict__ bf,
    const float* __restrict__ Wi, const float* __restrict__ bi,
    const float* __restrict__ Wc, const float* __restrict__ bc,
    const float* __restrict__ Wo, const float* __restrict__ bo,
    const float* __restrict__ Wy, const float* __restrict__ by,
    float* __restrict__ out)
{
    extern __shared__ float sm[];
    const int blk = blockIdx.x, t = threadIdx.x;
    const int wrp = t >> 5, lane = t & 31;
    float* yout = out;
    float* hout = out + (size_t)Bn * Sn * On;
    float* cout = hout + (size_t)Bn * Hn;

    // column offset owned by the reducing lane within a warp (lane%8==0 stores)
    const int redcol = ((lane & 8) ? 16 : 0) + ((lane & 16) ? 8 : 0);
    const int u  = wrp & 7;                // unit / col-group within CTA
    const int kh = wrp >> 3;               // k-half
    // per-warp row-phase stagger; distinct among the 4 warps of each SMSP
    const int stag = (2 * (wrp & 3) + (wrp >> 2)) & 7;

    if (blk < NG) {
        // -------- gate CTA: warp (u,kh) -> unit n0+u, 4 gates, K-half kh --------
        float* sA = sm;
        float* sP = sm + 2 * RC * G_ROW;   // two k-half planes of 32 x P_LD
        const int n0 = blk * 8;

        // Stationary weights: 4 cols x 24 k = 48 packed pairs (96 regs)
        unsigned long long wreg[48];
        {
            const float* b0 = Wf + (size_t)(n0 + u) * COMBn + kh * 768 + lane * G_K;
            const float* b1 = Wi + (size_t)(n0 + u) * COMBn + kh * 768 + lane * G_K;
            const float* b2 = Wc + (size_t)(n0 + u) * COMBn + kh * 768 + lane * G_K;
            const float* b3 = Wo + (size_t)(n0 + u) * COMBn + kh * 768 + lane * G_K;
#pragma unroll
            for (int j = 0; j < 12; ++j) {
                wreg[ 0 + j] = ((const unsigned long long*)b0)[j];
                wreg[12 + j] = ((const unsigned long long*)b1)[j];
                wreg[24 + j] = ((const unsigned long long*)b2)[j];
                wreg[36 + j] = ((const unsigned long long*)b3)[j];
            }
        }

        // combine-phase ownership: one (row, unit) element per thread
        const int cr = t >> 3, d = t & 7;
        float cell = c0[(size_t)cr * Hn + n0 + d];
        const float vbf = bf[n0 + d], vbi = bi[n0 + d], vbc = bc[n0 + d], vbo = bo[n0 + d];

#pragma unroll 1
        for (int it = 0; it < Sn; ++it) {
            const float* hsrc = (it == 0) ? h0 : (g_h + (size_t)(it & 1) * (Bn * Hn));

            auto stage = [&](int ch, int bsel) {
                float* dstb = sA + bsel * (RC * G_ROW);
#pragma unroll 1
                for (int i = t; i < RC * (COMBn / 4); i += NT) {   // 6 per thread
                    int rl  = i / (COMBn / 4);
                    int kc  = i - rl * (COMBn / 4);
                    int ssl = kc / (G_K / 4);
                    int off = kc - ssl * (G_K / 4);
                    int k   = kc * 4;
                    int r   = ch * RC + rl;
                    const float* src = (k < In)
                        ? (x + ((size_t)r * Sn + it) * In + k)
                        : (hsrc + (size_t)r * Hn + (k - In));
                    float* dst = dstb + rl * G_ROW + ssl * G_SLP + off * 4;
                    cp16((unsigned)__cvta_generic_to_shared(dst), src);
                }
            };

            stage(0, 0);
            cp_commit();
#pragma unroll 1
            for (int ch = 0; ch < NCH; ++ch) {
                cp_wait<0>();
                __syncthreads();               // single sync: data of ch ready AND
                                               // all warps done consuming ch-1
                if (ch + 1 < NCH) { stage(ch + 1, (ch + 1) & 1); cp_commit(); }
                const float* ab = sA + (ch & 1) * (RC * G_ROW) + (kh * 32 + lane) * G_SLP;
#pragma unroll 1
                for (int rq = 0; rq < RC; ++rq) {
                    int rr = (rq + stag) & 7;  // per-warp staggered row order
                    const ulonglong2* ap = (const ulonglong2*)(ab + rr * G_ROW);
                    unsigned long long a0 = 0, a1 = 0, a2 = 0, a3 = 0;
#pragma unroll
                    for (int j = 0; j < 6; ++j) {        // 6 LDS.128 -> 48 FMA2
                        ulonglong2 av = ap[j];
                        FMA2(a0, av.x, wreg[ 0 + 2 * j]);
                        FMA2(a1, av.x, wreg[12 + 2 * j]);
                        FMA2(a2, av.x, wreg[24 + 2 * j]);
                        FMA2(a3, av.x, wreg[36 + 2 * j]);
                        FMA2(a0, av.y, wreg[ 1 + 2 * j]);
                        FMA2(a1, av.y, wreg[13 + 2 * j]);
                        FMA2(a2, av.y, wreg[25 + 2 * j]);
                        FMA2(a3, av.y, wreg[37 + 2 * j]);
                    }
                    float red = reduce4(psum(a0), psum(a1), psum(a2), psum(a3), lane);
                    if ((lane & 7) == 0)
                        sP[kh * SP_PLANE + (u + redcol) * P_LD + ch * RC + rr] = red;
                }
            }
            __syncthreads();                   // all sP writes visible for combine

            // ---- combine: one (row, unit) per thread ----
            {
                float pf = sP[(d     ) * P_LD + cr] + sP[SP_PLANE + (d     ) * P_LD + cr];
                float pi = sP[( 8 + d) * P_LD + cr] + sP[SP_PLANE + ( 8 + d) * P_LD + cr];
                float pc = sP[(16 + d) * P_LD + cr] + sP[SP_PLANE + (16 + d) * P_LD + cr];
                float po = sP[(24 + d) * P_LD + cr] + sP[SP_PLANE + (24 + d) * P_LD + cr];
                float f = sigm(pf + vbf);
                float i = sigm(pi + vbi);
                float g = tanhf(pc + vbc);
                float o = sigm(po + vbo);
                cell = f * cell + i * g;
                float hh = o * tanhf(cell);
                g_h[(size_t)((it + 1) & 1) * (Bn * Hn) + (size_t)cr * Hn + n0 + d] = hh;
                if (it == Sn - 1) {
                    hout[(size_t)cr * Hn + n0 + d] = hh;
                    cout[(size_t)cr * Hn + n0 + d] = cell;
                }
            }
            grid_barrier();
        }
    } else {
        // -------- y CTA: warp (u,kh) -> cols {cy0+u,+8,+16,+24}, K-half kh; one step behind --------
        float* sA = sm;
        float* yP = sm + 2 * RC * Y_ROW;   // two k-half planes of 32 x P_LD
        const int cy0 = (blk - NG) * 32;

        unsigned long long wreg[32];       // 4 cols x 16 k = 32 pairs
        {
            const float* y0 = Wy + (size_t)(cy0 + u     ) * Hn + kh * 512 + lane * Y_K;
            const float* y1 = Wy + (size_t)(cy0 + u +  8) * Hn + kh * 512 + lane * Y_K;
            const float* y2 = Wy + (size_t)(cy0 + u + 16) * Hn + kh * 512 + lane * Y_K;
            const float* y3 = Wy + (size_t)(cy0 + u + 24) * Hn + kh * 512 + lane * Y_K;
#pragma unroll
            for (int j = 0; j < 8; ++j) {
                wreg[ 0 + j] = ((const unsigned long long*)y0)[j];
                wreg[ 8 + j] = ((const unsigned long long*)y1)[j];
                wreg[16 + j] = ((const unsigned long long*)y2)[j];
                wreg[24 + j] = ((const unsigned long long*)y3)[j];
            }
        }

#pragma unroll 1
        for (int it = 0; it <= Sn; ++it) {
            if (it >= 1) {
                const float* hsrc = g_h + (size_t)(it & 1) * (Bn * Hn);  // h^{(it)}

                auto stage = [&](int ch, int bsel) {
                    float* dstb = sA + bsel * (RC * Y_ROW);
#pragma unroll 1
                    for (int i = t; i < RC * (Hn / 4); i += NT) {   // 4 per thread
                        int rl  = i / (Hn / 4);
                        int kc  = i - rl * (Hn / 4);
                        int ssl = kc / (Y_K / 4);
                        int off = kc - ssl * (Y_K / 4);
                        int r   = ch * RC + rl;
                        const float* src = hsrc + (size_t)r * Hn + kc * 4;
                        float* dst = dstb + rl * Y_ROW + ssl * Y_SLP + off * 4;
                        cp16((unsigned)__cvta_generic_to_shared(dst), src);
                    }
                };

                stage(0, 0);
                cp_commit();
#pragma unroll 1
                for (int ch = 0; ch < NCH; ++ch) {
                    cp_wait<0>();
                    __syncthreads();
                    if (ch + 1 < NCH) { stage(ch + 1, (ch + 1) & 1); cp_commit(); }
                    const float* ab = sA + (ch & 1) * (RC * Y_ROW) + (kh * 32 + lane) * Y_SLP;
#pragma unroll 1
                    for (int rq = 0; rq < RC; ++rq) {
                        int rr = (rq + stag) & 7;
                        const ulonglong2* ap = (const ulonglong2*)(ab + rr * Y_ROW);
                        unsigned long long a0 = 0, a1 = 0, a2 = 0, a3 = 0;
#pragma unroll
                        for (int j = 0; j < 4; ++j) {     // 4 LDS.128 -> 32 FMA2
                            ulonglong2 av = ap[j];
                            FMA2(a0, av.x, wreg[ 0 + 2 * j]);
                            FMA2(a1, av.x, wreg[ 8 + 2 * j]);
                            FMA2(a2, av.x, wreg[16 + 2 * j]);
                            FMA2(a3, av.x, wreg[24 + 2 * j]);
                            FMA2(a0, av.y, wreg[ 1 + 2 * j]);
                            FMA2(a1, av.y, wreg[ 9 + 2 * j]);
                            FMA2(a2, av.y, wreg[17 + 2 * j]);
                            FMA2(a3, av.y, wreg[25 + 2 * j]);
                        }
                        float red = reduce4(psum(a0), psum(a1), psum(a2), psum(a3), lane);
                        if ((lane & 7) == 0)
                            yP[kh * SP_PLANE + (u + redcol) * P_LD + ch * RC + rr] = red;
                    }
                }
                __syncthreads();               // all yP writes visible

                // ---- combine halves + bias, store y_{it-1} ----
#pragma unroll 1
                for (int q = t; q < Bn * 32; q += NT) {   // 4 per thread
                    int r = q >> 5, col = q & 31;
                    float v = yP[col * P_LD + r] + yP[SP_PLANE + col * P_LD + r] + by[cy0 + col];
                    yout[((size_t)r * Sn + (it - 1)) * On + cy0 + col] = v;
                }
            }
            if (it < Sn) grid_barrier();
        }
    }
}

extern "C" void kernel_launch(void* const* d_in, const int* in_sizes, int n_in,
                              void* d_out, int out_size) {
    (void)in_sizes; (void)n_in; (void)out_size;
    const float* x  = (const float*)d_in[0];
    const float* h0 = (const float*)d_in[1];
    const float* c0 = (const float*)d_in[2];
    const float* Wf = (const float*)d_in[3];
    const float* bf = (const float*)d_in[4];
    const float* Wi = (const float*)d_in[5];
    const float* bi = (const float*)d_in[6];
    const float* Wc = (const float*)d_in[7];
    const float* bc = (const float*)d_in[8];
    const float* Wo = (const float*)d_in[9];
    const float* bo = (const float*)d_in[10];
    const float* Wy = (const float*)d_in[11];
    const float* by = (const float*)d_in[12];
    float* out = (float*)d_out;

    cudaFuncSetAttribute(lstm_fused, cudaFuncAttributeMaxDynamicSharedMemorySize, SMEM_BYTES);
    lstm_fused<<<NB, NT, SMEM_BYTES>>>(x, h0, c0, Wf, bf, Wi, bi, Wc, bc, Wo, bo, Wy, by, out);
}

// round 14
// speedup vs baseline: 1.6877x; 1.6877x over previous
#include <cuda_runtime.h>
#include <cuda_bf16.h>
#include <cstdint>
#include <cstddef>

namespace {
constexpr int Bn=64,Sn=512,Hn=1024,On=512;
constexpr int NG=128,NB=144,NTH=256;
constexpr int ABUF=17408;              // 64 rows * 272B
constexpr int WBUF=8704;               // 32 rows * 272B
constexpr int BUF=2*ABUF+2*WBUF;       // 52224
constexpr int REDO=2*BUF;              // 104448
constexpr int PLANE=2176;              // floats per warp plane (64*34)
constexpr int SBYO=REDO+8*PLANE*4;     // 174080
constexpr int SMEMSZ=SBYO+128;         // 174208
}

__device__ __align__(16) __nv_bfloat16 g_Wg_hi[6291456];   // 128*12*32*128
__device__ __align__(16) __nv_bfloat16 g_Wg_lo[6291456];
__device__ __align__(16) __nv_bfloat16 g_Wy_hi[524288];    // 16*8*32*128
__device__ __align__(16) __nv_bfloat16 g_Wy_lo[524288];
__device__ __align__(16) __nv_bfloat16 g_xA_hi[16777216];  // 512*4*64*128
__device__ __align__(16) __nv_bfloat16 g_xA_lo[16777216];
__device__ __align__(16) __nv_bfloat16 g_hA_hi[131072];    // 2*8*64*128
__device__ __align__(16) __nv_bfloat16 g_hA_lo[131072];
__device__ unsigned g_count=0;
__device__ volatile unsigned g_gen=0;

static __device__ __forceinline__ void cp16(unsigned dst,const void* src){
    asm volatile("cp.async.cg.shared.global [%0], [%1], 16;"::"r"(dst),"l"(src));}
static __device__ __forceinline__ void cp_commit(){
    asm volatile("cp.async.commit_group;":::"memory");}
template<int N> static __device__ __forceinline__ void cp_wait(){
    asm volatile("cp.async.wait_group %0;"::"n"(N):"memory");}

#define LDM4(r0,r1,r2,r3,addr) \
    asm volatile("ldmatrix.sync.aligned.m8n8.x4.shared.b16 {%0,%1,%2,%3}, [%4];" \
        : "=r"(r0),"=r"(r1),"=r"(r2),"=r"(r3) : "r"(addr))

#define MMA(d,a0,a1,a2,a3,b0,b1) \
    asm volatile("mma.sync.aligned.m16n8k16.row.col.f32.bf16.bf16.f32 " \
        "{%0,%1,%2,%3},{%4,%5,%6,%7},{%8,%9},{%0,%1,%2,%3};" \
        : "+f"((d)[0]),"+f"((d)[1]),"+f"((d)[2]),"+f"((d)[3]) \
        : "r"(a0),"r"(a1),"r"(a2),"r"(a3),"r"(b0),"r"(b1))

static __device__ __forceinline__ float sigm(float v){return 1.0f/(1.0f+__expf(-v));}

static __device__ __forceinline__ void grid_barrier(){
    __syncthreads();
    if(threadIdx.x==0){
        __threadfence();
        unsigned my=g_gen;
        if(atomicAdd(&g_count,1u)==(unsigned)(NB-1)){g_count=0u;__threadfence();g_gen=my+1u;}
        else{while(g_gen==my){} __threadfence();}
    }
    __syncthreads();
}

// ---- prologue: fp32 -> bf16 hi/lo chunk layouts (row-major 128-el rows) ----
__global__ void prep_kernel(const float* __restrict__ Wf,const float* __restrict__ Wi,
                            const float* __restrict__ Wc,const float* __restrict__ Wo,
                            const float* __restrict__ Wy,const float* __restrict__ x,
                            const float* __restrict__ h0){
    const long long NWg=4LL*1024*1536, NWy=512LL*1024, Nx=64LL*512*512, Nh=64LL*1024;
    const long long TOT=NWg+NWy+Nx+Nh;
    for(long long idx=(long long)blockIdx.x*blockDim.x+threadIdx.x; idx<TOT;
        idx+=(long long)gridDim.x*blockDim.x){
        float v; long long d; __nv_bfloat16 *hi,*lo;
        if(idx<NWg){
            int g=(int)(idx/(1024*1536)); int r2=(int)(idx%(1024*1536));
            int n=r2/1536,k=r2%1536;
            const float* W=(g==0)?Wf:(g==1)?Wi:(g==2)?Wc:Wo;
            v=W[(size_t)n*1536+k];
            int blk=n>>3, rr=g*8+(n&7), ch=k>>7, kk=k&127;
            d=(((long long)blk*12+ch)*32+rr)*128+kk; hi=g_Wg_hi; lo=g_Wg_lo;
        }else if(idx<NWg+NWy){
            int i2=(int)(idx-NWg); int o=i2/1024,k=i2%1024;
            v=Wy[(size_t)o*1024+k];
            int cy=o>>5, rr=o&31, ch=k>>7, kk=k&127;
            d=(((long long)cy*8+ch)*32+rr)*128+kk; hi=g_Wy_hi; lo=g_Wy_lo;
        }else if(idx<NWg+NWy+Nx){
            long long i2=idx-NWg-NWy;
            int r=(int)(i2/(512*512)),s=(int)((i2/512)%512),k=(int)(i2%512);
            v=x[i2];
            int ch=k>>7, kk=k&127;
            d=(((long long)s*4+ch)*64+r)*128+kk; hi=g_xA_hi; lo=g_xA_lo;
        }else{
            int i2=(int)(idx-NWg-NWy-Nx); int r=i2>>10,n=i2&1023;
            v=h0[i2];
            int ch=n>>7, kk=n&127;
            d=((long long)ch*64+r)*128+kk; hi=g_hA_hi; lo=g_hA_lo;   // phase 0
        }
        __nv_bfloat16 bh=__float2bfloat16_rn(v);
        hi[d]=bh; lo[d]=__float2bfloat16_rn(v-__bfloat162float(bh));
    }
}

// ---- persistent tensor-core LSTM ----
__global__ void __launch_bounds__(NTH,1) lstm_mma(
    const float* __restrict__ c0,
    const float* __restrict__ bf_,const float* __restrict__ bi_,
    const float* __restrict__ bc_,const float* __restrict__ bo_,
    const float* __restrict__ by_,float* __restrict__ out){
    extern __shared__ char smem[];
    const unsigned sb=(unsigned)__cvta_generic_to_shared(smem);
    const int blk=blockIdx.x,t=threadIdx.x,wrp=t>>5,lane=t&31;
    float* yout=out;
    float* hout=out+(size_t)Bn*Sn*On;
    float* cout=hout+(size_t)Bn*Hn;

    // ldmatrix per-lane address components
    const int arow=lane&15, aseg=(lane>>4)*16;              // A fragment rows/seg
    const int brow=((lane>>4)<<3)+(lane&7), bofs=((lane>>3)&1)*16;  // B fragment
    const unsigned kofs=wrp*32;                              // warp's 16-k slice (bytes)

    float acc[4][4][4];

    if(blk<NG){
        const int n0=blk*8;
        float cell[8],vbf[8],vbi[8],vbc[8],vbo[8];
        if(t<64){
#pragma unroll
            for(int d=0;d<8;++d){
                cell[d]=c0[(size_t)t*Hn+n0+d];
                vbf[d]=bf_[n0+d];vbi[d]=bi_[n0+d];vbc[d]=bc_[n0+d];vbo[d]=bo_[n0+d];
            }
        }
        auto stage=[&](int it2,int c,int b){
            const __nv_bfloat16 *ah,*al;
            if(c<4){ size_t o=((size_t)it2*4+c)*8192; ah=g_xA_hi+o; al=g_xA_lo+o; }
            else   { size_t o=((size_t)(it2&1)*8+(c-4))*8192; ah=g_hA_hi+o; al=g_hA_lo+o; }
            size_t wo=((size_t)blk*12+c)*4096;
            const __nv_bfloat16* wh=g_Wg_hi+wo; const __nv_bfloat16* wl=g_Wg_lo+wo;
            unsigned base=sb+b*BUF;
#pragma unroll 1
            for(int i=t;i<3072;i+=NTH){
                unsigned dst; const __nv_bfloat16* src;
                if(i<2048){ int hb=i>>10,row=(i>>4)&63,seg=i&15;
                    dst=base+hb*ABUF+row*272+seg*16; src=(hb?al:ah)+row*128+seg*8;
                }else{ int j=i-2048; int hb=j>>9,row=(j>>4)&31,seg=j&15;
                    dst=base+2*ABUF+hb*WBUF+row*272+seg*16; src=(hb?wl:wh)+row*128+seg*8; }
                cp16(dst,src);
            }
        };

#pragma unroll 1
        for(int it=0;it<Sn;++it){
#pragma unroll
            for(int m=0;m<4;++m)
#pragma unroll
                for(int n=0;n<4;++n)
#pragma unroll
                    for(int q=0;q<4;++q) acc[m][n][q]=0.0f;

            stage(it,0,0); cp_commit();
#pragma unroll 1
            for(int c=0;c<12;++c){
                cp_wait<0>(); __syncthreads();
                if(c<11){ stage(it,c+1,(c+1)&1); cp_commit(); }
                unsigned Ab=sb+(c&1)*BUF, Wb=Ab+2*ABUF;
                unsigned bh[8],bl[8];
                unsigned b0=Wb+brow*272+kofs+bofs;
                LDM4(bh[0],bh[1],bh[2],bh[3],b0);
                LDM4(bh[4],bh[5],bh[6],bh[7],b0+16*272);
                LDM4(bl[0],bl[1],bl[2],bl[3],b0+WBUF);
                LDM4(bl[4],bl[5],bl[6],bl[7],b0+WBUF+16*272);
                unsigned a0=Ab+arow*272+kofs+aseg;
#pragma unroll
                for(int m=0;m<4;++m){
                    unsigned ah0,ah1,ah2,ah3,al0,al1,al2,al3;
                    LDM4(ah0,ah1,ah2,ah3,a0+m*4352);
                    LDM4(al0,al1,al2,al3,a0+m*4352+ABUF);
#pragma unroll
                    for(int n=0;n<4;++n){
                        MMA(acc[m][n],ah0,ah1,ah2,ah3,bh[2*n],bh[2*n+1]);
                        MMA(acc[m][n],al0,al1,al2,al3,bh[2*n],bh[2*n+1]);
                        MMA(acc[m][n],ah0,ah1,ah2,ah3,bl[2*n],bl[2*n+1]);
                    }
                }
            }
            // write per-warp reduction plane
            {
                float* rp=(float*)(smem+REDO+wrp*(PLANE*4));
                int g=lane>>2,t2=lane&3;
#pragma unroll
                for(int m=0;m<4;++m)
#pragma unroll
                    for(int h=0;h<2;++h){
                        int r=16*m+8*h+g;
#pragma unroll
                        for(int n=0;n<4;++n)
                            *(float2*)&rp[r*34+8*n+2*t2]=
                                make_float2(acc[m][n][2*h],acc[m][n][2*h+1]);
                    }
            }
            __syncthreads();
            {   // reduce 8 planes into plane 0
                float* rp=(float*)(smem+REDO);
#pragma unroll 1
                for(int o=t;o<PLANE;o+=NTH){
                    float s=0.0f;
#pragma unroll
                    for(int w2=0;w2<8;++w2) s+=rp[w2*PLANE+o];
                    rp[o]=s;
                }
            }
            __syncthreads();
            if(t<64){
                const float* rp=(const float*)(smem+REDO);
                float P[32];
#pragma unroll
                for(int c2=0;c2<32;++c2) P[c2]=rp[t*34+c2];
                unsigned short hs[8],ls[8];
#pragma unroll
                for(int d=0;d<8;++d){
                    float f=sigm(P[d]+vbf[d]);
                    float ii=sigm(P[8+d]+vbi[d]);
                    float g=tanhf(P[16+d]+vbc[d]);
                    float o=sigm(P[24+d]+vbo[d]);
                    cell[d]=f*cell[d]+ii*g;
                    float hh=o*tanhf(cell[d]);
                    __nv_bfloat16 bh2=__float2bfloat16_rn(hh);
                    __nv_bfloat16 bl2=__float2bfloat16_rn(hh-__bfloat162float(bh2));
                    hs[d]=__bfloat16_as_ushort(bh2); ls[d]=__bfloat16_as_ushort(bl2);
                    if(it==Sn-1){ hout[(size_t)t*Hn+n0+d]=hh; cout[(size_t)t*Hn+n0+d]=cell[d]; }
                }
                int p1=(it+1)&1,hc=n0>>7,ko=n0&127;
                size_t eo=(((size_t)p1*8+hc)*64+t)*128+ko;
                uint4 vh=make_uint4(hs[0]|((unsigned)hs[1]<<16),hs[2]|((unsigned)hs[3]<<16),
                                    hs[4]|((unsigned)hs[5]<<16),hs[6]|((unsigned)hs[7]<<16));
                uint4 vl=make_uint4(ls[0]|((unsigned)ls[1]<<16),ls[2]|((unsigned)ls[3]<<16),
                                    ls[4]|((unsigned)ls[5]<<16),ls[6]|((unsigned)ls[7]<<16));
                *(uint4*)((char*)g_hA_hi+eo*2)=vh;
                *(uint4*)((char*)g_hA_lo+eo*2)=vl;
            }
            grid_barrier();
        }
    }else{
        const int cyj=blk-NG, cy0=cyj*32;
        float* sby=(float*)(smem+SBYO);
        if(t<32) sby[t]=by_[cy0+t];
        auto stage=[&](int p,int c,int b){
            size_t o=((size_t)p*8+c)*8192;
            const __nv_bfloat16* ah=g_hA_hi+o; const __nv_bfloat16* al=g_hA_lo+o;
            size_t wo=((size_t)cyj*8+c)*4096;
            const __nv_bfloat16* wh=g_Wy_hi+wo; const __nv_bfloat16* wl=g_Wy_lo+wo;
            unsigned base=sb+b*BUF;
#pragma unroll 1
            for(int i=t;i<3072;i+=NTH){
                unsigned dst; const __nv_bfloat16* src;
                if(i<2048){ int hb=i>>10,row=(i>>4)&63,seg=i&15;
                    dst=base+hb*ABUF+row*272+seg*16; src=(hb?al:ah)+row*128+seg*8;
                }else{ int j=i-2048; int hb=j>>9,row=(j>>4)&31,seg=j&15;
                    dst=base+2*ABUF+hb*WBUF+row*272+seg*16; src=(hb?wl:wh)+row*128+seg*8; }
                cp16(dst,src);
            }
        };
#pragma unroll 1
        for(int it=0;it<=Sn;++it){
            if(it>=1){
                int p=it&1;
#pragma unroll
                for(int m=0;m<4;++m)
#pragma unroll
                    for(int n=0;n<4;++n)
#pragma unroll
                        for(int q=0;q<4;++q) acc[m][n][q]=0.0f;
                stage(p,0,0); cp_commit();
#pragma unroll 1
                for(int c=0;c<8;++c){
                    cp_wait<0>(); __syncthreads();
                    if(c<7){ stage(p,c+1,(c+1)&1); cp_commit(); }
                    unsigned Ab=sb+(c&1)*BUF, Wb=Ab+2*ABUF;
                    unsigned bh[8],bl[8];
                    unsigned b0=Wb+brow*272+kofs+bofs;
                    LDM4(bh[0],bh[1],bh[2],bh[3],b0);
                    LDM4(bh[4],bh[5],bh[6],bh[7],b0+16*272);
                    LDM4(bl[0],bl[1],bl[2],bl[3],b0+WBUF);
                    LDM4(bl[4],bl[5],bl[6],bl[7],b0+WBUF+16*272);
                    unsigned a0=Ab+arow*272+kofs+aseg;
#pragma unroll
                    for(int m=0;m<4;++m){
                        unsigned ah0,ah1,ah2,ah3,al0,al1,al2,al3;
                        LDM4(ah0,ah1,ah2,ah3,a0+m*4352);
                        LDM4(al0,al1,al2,al3,a0+m*4352+ABUF);
#pragma unroll
                        for(int n=0;n<4;++n){
                            MMA(acc[m][n],ah0,ah1,ah2,ah3,bh[2*n],bh[2*n+1]);
                            MMA(acc[m][n],al0,al1,al2,al3,bh[2*n],bh[2*n+1]);
                            MMA(acc[m][n],ah0,ah1,ah2,ah3,bl[2*n],bl[2*n+1]);
                        }
                    }
                }
                {
                    float* rp=(float*)(smem+REDO+wrp*(PLANE*4));
                    int g=lane>>2,t2=lane&3;
#pragma unroll
                    for(int m=0;m<4;++m)
#pragma unroll
                        for(int h=0;h<2;++h){
                            int r=16*m+8*h+g;
#pragma unroll
                            for(int n=0;n<4;++n)
                                *(float2*)&rp[r*34+8*n+2*t2]=
                                    make_float2(acc[m][n][2*h],acc[m][n][2*h+1]);
                        }
                }
                __syncthreads();
                {
                    float* rp=(float*)(smem+REDO);
#pragma unroll 1
                    for(int o=t;o<PLANE;o+=NTH){
                        float s=0.0f;
#pragma unroll
                        for(int w2=0;w2<8;++w2) s+=rp[w2*PLANE+o];
                        rp[o]=s;
                    }
                }
                __syncthreads();
                if(t<64){
                    const float* rp=(const float*)(smem+REDO);
#pragma unroll
                    for(int c2=0;c2<32;++c2)
                        yout[((size_t)t*Sn+(it-1))*On+cy0+c2]=rp[t*34+c2]+sby[c2];
                }
            }
            if(it<Sn) grid_barrier();
        }
    }
}

extern "C" void kernel_launch(void* const* d_in, const int* in_sizes, int n_in,
                              void* d_out, int out_size){
    (void)in_sizes;(void)n_in;(void)out_size;
    const float* x =(const float*)d_in[0];
    const float* h0=(const float*)d_in[1];
    const float* c0=(const float*)d_in[2];
    const float* Wf=(const float*)d_in[3];
    const float* bf=(const float*)d_in[4];
    const float* Wi=(const float*)d_in[5];
    const float* bi=(const float*)d_in[6];
    const float* Wc=(const float*)d_in[7];
    const float* bc=(const float*)d_in[8];
    const float* Wo=(const float*)d_in[9];
    const float* bo=(const float*)d_in[10];
    const float* Wy=(const float*)d_in[11];
    const float* by=(const float*)d_in[12];
    float* out=(float*)d_out;
    prep_kernel<<<4096,256>>>(Wf,Wi,Wc,Wo,Wy,x,h0);
    cudaFuncSetAttribute(lstm_mma,cudaFuncAttributeMaxDynamicSharedMemorySize,SMEMSZ);
    lstm_mma<<<NB,NTH,SMEMSZ>>>(c0,bf,bi,bc,bo,by,out);
}

// round 15
// speedup vs baseline: 1.9015x; 1.1266x over previous
#include <cuda_runtime.h>
#include <cuda_bf16.h>
#include <cstdint>
#include <cstddef>

namespace {
constexpr int Bn=64,Sn=512,Hn=1024,On=512;
constexpr int NG=128,NB=144,NTH=512;
constexpr int ABUF=17408;              // 64 rows * 272B
constexpr int WBUF=8704;               // 32 rows * 272B
constexpr int BUF=2*ABUF+2*WBUF;       // 52224
constexpr int NSTG=3;
constexpr int REDO=NSTG*BUF;           // 156672
constexpr int PLANEF=32*34;            // floats per warp plane (1088)
constexpr int SBYO=REDO+16*PLANEF*4;   // 226304
constexpr int SMEMSZ=SBYO+128;         // 226432
}

__device__ __align__(16) __nv_bfloat16 g_Wg_hi[6291456];   // 128*12*32*128
__device__ __align__(16) __nv_bfloat16 g_Wg_lo[6291456];
__device__ __align__(16) __nv_bfloat16 g_Wy_hi[524288];    // 16*8*32*128
__device__ __align__(16) __nv_bfloat16 g_Wy_lo[524288];
__device__ __align__(16) __nv_bfloat16 g_xA_hi[16777216];  // 512*4*64*128
__device__ __align__(16) __nv_bfloat16 g_xA_lo[16777216];
__device__ __align__(16) __nv_bfloat16 g_hA_hi[131072];    // 2*8*64*128
__device__ __align__(16) __nv_bfloat16 g_hA_lo[131072];
__device__ unsigned g_count=0;
__device__ volatile unsigned g_gen=0;

static __device__ __forceinline__ void cp16(unsigned dst,const void* src){
    asm volatile("cp.async.cg.shared.global [%0], [%1], 16;"::"r"(dst),"l"(src));}
static __device__ __forceinline__ void cp_commit(){
    asm volatile("cp.async.commit_group;":::"memory");}
template<int N> static __device__ __forceinline__ void cp_wait(){
    asm volatile("cp.async.wait_group %0;"::"n"(N):"memory");}

#define LDM4(r0,r1,r2,r3,addr) \
    asm volatile("ldmatrix.sync.aligned.m8n8.x4.shared.b16 {%0,%1,%2,%3}, [%4];" \
        : "=r"(r0),"=r"(r1),"=r"(r2),"=r"(r3) : "r"(addr))

#define MMA(d,a0,a1,a2,a3,b0,b1) \
    asm volatile("mma.sync.aligned.m16n8k16.row.col.f32.bf16.bf16.f32 " \
        "{%0,%1,%2,%3},{%4,%5,%6,%7},{%8,%9},{%0,%1,%2,%3};" \
        : "+f"((d)[0]),"+f"((d)[1]),"+f"((d)[2]),"+f"((d)[3]) \
        : "r"(a0),"r"(a1),"r"(a2),"r"(a3),"r"(b0),"r"(b1))

static __device__ __forceinline__ float sigm(float v){return 1.0f/(1.0f+__expf(-v));}

static __device__ __forceinline__ void grid_barrier(){
    __syncthreads();
    if(threadIdx.x==0){
        __threadfence();
        unsigned my=g_gen;
        if(atomicAdd(&g_count,1u)==(unsigned)(NB-1)){g_count=0u;__threadfence();g_gen=my+1u;}
        else{while(g_gen==my){} __threadfence();}
    }
    __syncthreads();
}

// ---- prologue: fp32 -> bf16 hi/lo chunk layouts (row-major 128-el rows) ----
__global__ void prep_kernel(const float* __restrict__ Wf,const float* __restrict__ Wi,
                            const float* __restrict__ Wc,const float* __restrict__ Wo,
                            const float* __restrict__ Wy,const float* __restrict__ x,
                            const float* __restrict__ h0){
    const long long NWg=4LL*1024*1536, NWy=512LL*1024, Nx=64LL*512*512, Nh=64LL*1024;
    const long long TOT=NWg+NWy+Nx+Nh;
    for(long long idx=(long long)blockIdx.x*blockDim.x+threadIdx.x; idx<TOT;
        idx+=(long long)gridDim.x*blockDim.x){
        float v; long long d; __nv_bfloat16 *hi,*lo;
        if(idx<NWg){
            int g=(int)(idx/(1024*1536)); int r2=(int)(idx%(1024*1536));
            int n=r2/1536,k=r2%1536;
            const float* W=(g==0)?Wf:(g==1)?Wi:(g==2)?Wc:Wo;
            v=W[(size_t)n*1536+k];
            int blk=n>>3, rr=g*8+(n&7), ch=k>>7, kk=k&127;
            d=(((long long)blk*12+ch)*32+rr)*128+kk; hi=g_Wg_hi; lo=g_Wg_lo;
        }else if(idx<NWg+NWy){
            int i2=(int)(idx-NWg); int o=i2/1024,k=i2%1024;
            v=Wy[(size_t)o*1024+k];
            int cy=o>>5, rr=o&31, ch=k>>7, kk=k&127;
            d=(((long long)cy*8+ch)*32+rr)*128+kk; hi=g_Wy_hi; lo=g_Wy_lo;
        }else if(idx<NWg+NWy+Nx){
            long long i2=idx-NWg-NWy;
            int r=(int)(i2/(512*512)),s=(int)((i2/512)%512),k=(int)(i2%512);
            v=x[i2];
            int ch=k>>7, kk=k&127;
            d=(((long long)s*4+ch)*64+r)*128+kk; hi=g_xA_hi; lo=g_xA_lo;
        }else{
            int i2=(int)(idx-NWg-NWy-Nx); int r=i2>>10,n=i2&1023;
            v=h0[i2];
            int ch=n>>7, kk=n&127;
            d=((long long)ch*64+r)*128+kk; hi=g_hA_hi; lo=g_hA_lo;   // phase 0
        }
        __nv_bfloat16 bh=__float2bfloat16_rn(v);
        hi[d]=bh; lo[d]=__float2bfloat16_rn(v-__bfloat162float(bh));
    }
}

// ---- persistent tensor-core LSTM, 16 warps, 3-stage pipeline ----
__global__ void __launch_bounds__(NTH,1) lstm_mma(
    const float* __restrict__ c0,
    const float* __restrict__ bf_,const float* __restrict__ bi_,
    const float* __restrict__ bc_,const float* __restrict__ bo_,
    const float* __restrict__ by_,float* __restrict__ out){
    extern __shared__ char smem[];
    const unsigned sb=(unsigned)__cvta_generic_to_shared(smem);
    const int blk=blockIdx.x,t=threadIdx.x,wrp=t>>5,lane=t&31;
    float* yout=out;
    float* hout=out+(size_t)Bn*Sn*On;
    float* cout=hout+(size_t)Bn*Hn;

    const int wm=wrp&1, wk=wrp>>1;          // M-half, k-slice
    const unsigned kofs=wk*32;              // 16 k elems = 32 bytes
    const int arow=lane&15, aseg=(lane>>4)*16;
    const int brow=((lane>>4)<<3)+(lane&7), bofs=((lane>>3)&1)*16;

    float acc[2][4][4];

    if(blk<NG){
        const int n0=blk*8;
        float cell[8],vbf[8],vbi[8],vbc[8],vbo[8];
        if(t<64){
#pragma unroll
            for(int d=0;d<8;++d){
                cell[d]=c0[(size_t)t*Hn+n0+d];
                vbf[d]=bf_[n0+d];vbi[d]=bi_[n0+d];vbc[d]=bc_[n0+d];vbo[d]=bo_[n0+d];
            }
        }
        auto stage=[&](int it2,int c,int b){
            const __nv_bfloat16 *ah,*al;
            if(c<4){ size_t o=((size_t)it2*4+c)*8192; ah=g_xA_hi+o; al=g_xA_lo+o; }
            else   { size_t o=((size_t)(it2&1)*8+(c-4))*8192; ah=g_hA_hi+o; al=g_hA_lo+o; }
            size_t wo=((size_t)blk*12+c)*4096;
            const __nv_bfloat16* wh=g_Wg_hi+wo; const __nv_bfloat16* wl=g_Wg_lo+wo;
            unsigned base=sb+b*BUF;
#pragma unroll 1
            for(int i=t;i<3072;i+=NTH){
                unsigned dst; const __nv_bfloat16* src;
                if(i<2048){ int hb=i>>10,row=(i>>4)&63,seg=i&15;
                    dst=base+hb*ABUF+row*272+seg*16; src=(hb?al:ah)+row*128+seg*8;
                }else{ int j=i-2048; int hb=j>>9,row=(j>>4)&31,seg=j&15;
                    dst=base+2*ABUF+hb*WBUF+row*272+seg*16; src=(hb?wl:wh)+row*128+seg*8; }
                cp16(dst,src);
            }
        };

#pragma unroll 1
        for(int it=0;it<Sn;++it){
#pragma unroll
            for(int m=0;m<2;++m)
#pragma unroll
                for(int n=0;n<4;++n)
#pragma unroll
                    for(int q=0;q<4;++q) acc[m][n][q]=0.0f;

            stage(it,0,0); cp_commit();
            stage(it,1,1); cp_commit();
#pragma unroll 1
            for(int c=0;c<12;++c){
                if(c<11) cp_wait<1>(); else cp_wait<0>();
                __syncthreads();
                if(c+2<12){ int b=(c+2)%NSTG; stage(it,c+2,b); cp_commit(); }
                unsigned Ab=sb+(c%NSTG)*BUF, Wb=Ab+2*ABUF;
                unsigned bh[8],bl[8];
                unsigned b0=Wb+brow*272+kofs+bofs;
                LDM4(bh[0],bh[1],bh[2],bh[3],b0);
                LDM4(bh[4],bh[5],bh[6],bh[7],b0+16*272);
                LDM4(bl[0],bl[1],bl[2],bl[3],b0+WBUF);
                LDM4(bl[4],bl[5],bl[6],bl[7],b0+WBUF+16*272);
                unsigned a0=Ab+(wm*32+arow)*272+kofs+aseg;
#pragma unroll
                for(int m=0;m<2;++m){
                    unsigned ah0,ah1,ah2,ah3,al0,al1,al2,al3;
                    LDM4(ah0,ah1,ah2,ah3,a0+m*4352);
                    LDM4(al0,al1,al2,al3,a0+m*4352+ABUF);
#pragma unroll
                    for(int n=0;n<4;++n){
                        MMA(acc[m][n],ah0,ah1,ah2,ah3,bh[2*n],bh[2*n+1]);
                        MMA(acc[m][n],al0,al1,al2,al3,bh[2*n],bh[2*n+1]);
                        MMA(acc[m][n],ah0,ah1,ah2,ah3,bl[2*n],bl[2*n+1]);
                    }
                }
            }
            // per-warp plane (plane index = wrp; rows are this warp's M-half)
            {
                float* rp=(float*)(smem+REDO+wrp*(PLANEF*4));
                int g=lane>>2,t2=lane&3;
#pragma unroll
                for(int m=0;m<2;++m)
#pragma unroll
                    for(int h=0;h<2;++h){
                        int r=16*m+8*h+g;
#pragma unroll
                        for(int n=0;n<4;++n)
                            *(float2*)&rp[r*34+8*n+2*t2]=
                                make_float2(acc[m][n][2*h],acc[m][n][2*h+1]);
                    }
            }
            __syncthreads();
            {   // reduce 16 planes -> 64x34 at plane-0/1 region (alias-safe)
                float* rb=(float*)(smem+REDO);
#pragma unroll 1
                for(int o=t;o<64*34;o+=NTH){
                    int R=o/34,c2=o-R*34,wm2=R>>5,r=R&31;
                    float s=0.0f;
#pragma unroll
                    for(int wk2=0;wk2<8;++wk2) s+=rb[(wk2*2+wm2)*PLANEF+r*34+c2];
                    rb[o]=s;
                }
            }
            __syncthreads();
            if(t<64){
                const float* rb=(const float*)(smem+REDO);
                float P[32];
#pragma unroll
                for(int c2=0;c2<32;++c2) P[c2]=rb[t*34+c2];
                unsigned short hs[8],ls[8];
#pragma unroll
                for(int d=0;d<8;++d){
                    float f=sigm(P[d]+vbf[d]);
                    float ii=sigm(P[8+d]+vbi[d]);
                    float g=tanhf(P[16+d]+vbc[d]);
                    float o=sigm(P[24+d]+vbo[d]);
                    cell[d]=f*cell[d]+ii*g;
                    float hh=o*tanhf(cell[d]);
                    __nv_bfloat16 bh2=__float2bfloat16_rn(hh);
                    __nv_bfloat16 bl2=__float2bfloat16_rn(hh-__bfloat162float(bh2));
                    hs[d]=__bfloat16_as_ushort(bh2); ls[d]=__bfloat16_as_ushort(bl2);
                    if(it==Sn-1){ hout[(size_t)t*Hn+n0+d]=hh; cout[(size_t)t*Hn+n0+d]=cell[d]; }
                }
                int p1=(it+1)&1,hc=n0>>7,ko=n0&127;
                size_t eo=(((size_t)p1*8+hc)*64+t)*128+ko;
                uint4 vh=make_uint4(hs[0]|((unsigned)hs[1]<<16),hs[2]|((unsigned)hs[3]<<16),
                                    hs[4]|((unsigned)hs[5]<<16),hs[6]|((unsigned)hs[7]<<16));
                uint4 vl=make_uint4(ls[0]|((unsigned)ls[1]<<16),ls[2]|((unsigned)ls[3]<<16),
                                    ls[4]|((unsigned)ls[5]<<16),ls[6]|((unsigned)ls[7]<<16));
                *(uint4*)((char*)g_hA_hi+eo*2)=vh;
                *(uint4*)((char*)g_hA_lo+eo*2)=vl;
            }
            grid_barrier();
        }
    }else{
        const int cyj=blk-NG, cy0=cyj*32;
        float* sby=(float*)(smem+SBYO);
        if(t<32) sby[t]=by_[cy0+t];
        auto stage=[&](int p,int c,int b){
            size_t o=((size_t)p*8+c)*8192;
            const __nv_bfloat16* ah=g_hA_hi+o; const __nv_bfloat16* al=g_hA_lo+o;
            size_t wo=((size_t)cyj*8+c)*4096;
            const __nv_bfloat16* wh=g_Wy_hi+wo; const __nv_bfloat16* wl=g_Wy_lo+wo;
            unsigned base=sb+b*BUF;
#pragma unroll 1
            for(int i=t;i<3072;i+=NTH){
                unsigned dst; const __nv_bfloat16* src;
                if(i<2048){ int hb=i>>10,row=(i>>4)&63,seg=i&15;
                    dst=base+hb*ABUF+row*272+seg*16; src=(hb?al:ah)+row*128+seg*8;
                }else{ int j=i-2048; int hb=j>>9,row=(j>>4)&31,seg=j&15;
                    dst=base+2*ABUF+hb*WBUF+row*272+seg*16; src=(hb?wl:wh)+row*128+seg*8; }
                cp16(dst,src);
            }
        };
#pragma unroll 1
        for(int it=0;it<=Sn;++it){
            if(it>=1){
                int p=it&1;
#pragma unroll
                for(int m=0;m<2;++m)
#pragma unroll
                    for(int n=0;n<4;++n)
#pragma unroll
                        for(int q=0;q<4;++q) acc[m][n][q]=0.0f;
                stage(p,0,0); cp_commit();
                stage(p,1,1); cp_commit();
#pragma unroll 1
                for(int c=0;c<8;++c){
                    if(c<7) cp_wait<1>(); else cp_wait<0>();
                    __syncthreads();
                    if(c+2<8){ int b=(c+2)%NSTG; stage(p,c+2,b); cp_commit(); }
                    unsigned Ab=sb+(c%NSTG)*BUF, Wb=Ab+2*ABUF;
                    unsigned bh[8],bl[8];
                    unsigned b0=Wb+brow*272+kofs+bofs;
                    LDM4(bh[0],bh[1],bh[2],bh[3],b0);
                    LDM4(bh[4],bh[5],bh[6],bh[7],b0+16*272);
                    LDM4(bl[0],bl[1],bl[2],bl[3],b0+WBUF);
                    LDM4(bl[4],bl[5],bl[6],bl[7],b0+WBUF+16*272);
                    unsigned a0=Ab+(wm*32+arow)*272+kofs+aseg;
#pragma unroll
                    for(int m=0;m<2;++m){
                        unsigned ah0,ah1,ah2,ah3,al0,al1,al2,al3;
                        LDM4(ah0,ah1,ah2,ah3,a0+m*4352);
                        LDM4(al0,al1,al2,al3,a0+m*4352+ABUF);
#pragma unroll
                        for(int n=0;n<4;++n){
                            MMA(acc[m][n],ah0,ah1,ah2,ah3,bh[2*n],bh[2*n+1]);
                            MMA(acc[m][n],al0,al1,al2,al3,bh[2*n],bh[2*n+1]);
                            MMA(acc[m][n],ah0,ah1,ah2,ah3,bl[2*n],bl[2*n+1]);
                        }
                    }
                }
                {
                    float* rp=(float*)(smem+REDO+wrp*(PLANEF*4));
                    int g=lane>>2,t2=lane&3;
#pragma unroll
                    for(int m=0;m<2;++m)
#pragma unroll
                        for(int h=0;h<2;++h){
                            int r=16*m+8*h+g;
#pragma unroll
                            for(int n=0;n<4;++n)
                                *(float2*)&rp[r*34+8*n+2*t2]=
                                    make_float2(acc[m][n][2*h],acc[m][n][2*h+1]);
                        }
                }
                __syncthreads();
                {
                    float* rb=(float*)(smem+REDO);
#pragma unroll 1
                    for(int o=t;o<64*34;o+=NTH){
                        int R=o/34,c2=o-R*34,wm2=R>>5,r=R&31;
                        float s=0.0f;
#pragma unroll
                        for(int wk2=0;wk2<8;++wk2) s+=rb[(wk2*2+wm2)*PLANEF+r*34+c2];
                        rb[o]=s;
                    }
                }
                __syncthreads();
                if(t<64){
                    const float* rb=(const float*)(smem+REDO);
#pragma unroll
                    for(int c2=0;c2<32;++c2)
                        yout[((size_t)t*Sn+(it-1))*On+cy0+c2]=rb[t*34+c2]+sby[c2];
                }
            }
            if(it<Sn) grid_barrier();
        }
    }
}

extern "C" void kernel_launch(void* const* d_in, const int* in_sizes, int n_in,
                              void* d_out, int out_size){
    (void)in_sizes;(void)n_in;(void)out_size;
    const float* x =(const float*)d_in[0];
    const float* h0=(const float*)d_in[1];
    const float* c0=(const float*)d_in[2];
    const float* Wf=(const float*)d_in[3];
    const float* bf=(const float*)d_in[4];
    const float* Wi=(const float*)d_in[5];
    const float* bi=(const float*)d_in[6];
    const float* Wc=(const float*)d_in[7];
    const float* bc=(const float*)d_in[8];
    const float* Wo=(const float*)d_in[9];
    const float* bo=(const float*)d_in[10];
    const float* Wy=(const float*)d_in[11];
    const float* by=(const float*)d_in[12];
    float* out=(float*)d_out;
    prep_kernel<<<4096,256>>>(Wf,Wi,Wc,Wo,Wy,x,h0);
    cudaFuncSetAttribute(lstm_mma,cudaFuncAttributeMaxDynamicSharedMemorySize,SMEMSZ);
    lstm_mma<<<NB,NTH,SMEMSZ>>>(c0,bf,bi,bc,bo,by,out);
}